// round 2
// baseline (speedup 1.0000x reference)
#include <cuda_runtime.h>
#include <cuda_bf16.h>
#include <math.h>

// Problem constants
#define BB 2
#define TT 2048
#define EE 1024
#define HH 16
#define DD 64
#define VV 32000
#define BT (BB * TT)   // 4096

// ---------------- scratch (device globals; no allocations allowed) ------------
__device__ float g_x[BT * EE];
__device__ float g_q[BT * EE];
__device__ float g_k[BT * EE];
__device__ float g_v[BT * EE];
__device__ float g_o[BT * EE];
__device__ float g_lterms[BT];

// ---------------- embedding: x = tok_table[tokens] + pos_emb ------------------
__global__ void embed_kernel(const int* __restrict__ tokens,
                             const float* __restrict__ tok_table,
                             const float* __restrict__ pos_emb,
                             float* __restrict__ x) {
    int idx = blockIdx.x * blockDim.x + threadIdx.x;  // over BT*EE
    int bt = idx >> 10;          // /EE
    int e  = idx & (EE - 1);
    int t  = bt & (TT - 1);      // bt % TT
    int tok = tokens[bt];
    x[idx] = tok_table[tok * EE + e] + pos_emb[t * EE + e];
}

// ---------------- NT SGEMM: C[m,n] = sum_k A[m,k]*B[n,k] + bias[n] ------------
// BM=BN=128, BK=16, 256 threads, 8x8 per-thread tile.
__global__ __launch_bounds__(256) void gemm_nt(const float* __restrict__ A,
                                               const float* __restrict__ B,
                                               const float* __restrict__ bias,
                                               float* __restrict__ C,
                                               int M, int N, int K) {
    __shared__ float As[16][128];
    __shared__ float Bs[16][128];

    int bm = blockIdx.y * 128;
    int bn = blockIdx.x * 128;
    int tid = threadIdx.x;

    int warp = tid >> 5, lane = tid & 31;
    int wr = warp >> 1, wc = warp & 1;   // 4x2 warps
    int lr = lane >> 3, lc = lane & 7;   // 4x8 lanes
    int row0 = wr * 32 + lr * 8;         // 0..127 step 8
    int col0 = wc * 64 + lc * 8;         // 0..127 step 8

    float acc[8][8];
#pragma unroll
    for (int i = 0; i < 8; i++)
#pragma unroll
        for (int j = 0; j < 8; j++) acc[i][j] = 0.0f;

    int lrow = tid >> 2;            // 0..63
    int lk   = (tid & 3) << 2;      // 0,4,8,12

    const float* Aptr = A + (size_t)(bm + lrow) * K + lk;
    const float* Bptr = B + (size_t)(bn + lrow) * K + lk;
    size_t half = (size_t)64 * K;

    for (int k0 = 0; k0 < K; k0 += 16) {
        float4 a0 = *(const float4*)(Aptr);
        float4 a1 = *(const float4*)(Aptr + half);
        float4 b0 = *(const float4*)(Bptr);
        float4 b1 = *(const float4*)(Bptr + half);

        As[lk + 0][lrow] = a0.x; As[lk + 1][lrow] = a0.y;
        As[lk + 2][lrow] = a0.z; As[lk + 3][lrow] = a0.w;
        As[lk + 0][lrow + 64] = a1.x; As[lk + 1][lrow + 64] = a1.y;
        As[lk + 2][lrow + 64] = a1.z; As[lk + 3][lrow + 64] = a1.w;

        Bs[lk + 0][lrow] = b0.x; Bs[lk + 1][lrow] = b0.y;
        Bs[lk + 2][lrow] = b0.z; Bs[lk + 3][lrow] = b0.w;
        Bs[lk + 0][lrow + 64] = b1.x; Bs[lk + 1][lrow + 64] = b1.y;
        Bs[lk + 2][lrow + 64] = b1.z; Bs[lk + 3][lrow + 64] = b1.w;

        __syncthreads();

#pragma unroll
        for (int kk = 0; kk < 16; kk++) {
            float a[8], b[8];
            *(float4*)&a[0] = *(const float4*)&As[kk][row0];
            *(float4*)&a[4] = *(const float4*)&As[kk][row0 + 4];
            *(float4*)&b[0] = *(const float4*)&Bs[kk][col0];
            *(float4*)&b[4] = *(const float4*)&Bs[kk][col0 + 4];
#pragma unroll
            for (int i = 0; i < 8; i++)
#pragma unroll
                for (int j = 0; j < 8; j++) acc[i][j] = fmaf(a[i], b[j], acc[i][j]);
        }
        __syncthreads();

        Aptr += 16;
        Bptr += 16;
    }

#pragma unroll
    for (int i = 0; i < 8; i++) {
        size_t crow = (size_t)(bm + row0 + i) * N + bn + col0;
#pragma unroll
        for (int j = 0; j < 8; j++)
            C[crow + j] = acc[i][j] + bias[bn + col0 + j];
    }
}

// ---------------- causal attention (flash-style, online softmax) --------------
// One block = 16 query rows of one (b,h). KV tiles of 64 rows. 256 threads.
// quirk: scale AFTER softmax -> final O *= 1/sqrt(D) = 0.125
#define AT_TQ 16
#define AT_TS 64

__global__ __launch_bounds__(256) void attn_kernel(const float* __restrict__ q,
                                                   const float* __restrict__ k,
                                                   const float* __restrict__ v,
                                                   float* __restrict__ o) {
    int qt0 = blockIdx.x * AT_TQ;
    int h = blockIdx.y;
    int b = blockIdx.z;

    __shared__ float Qs[AT_TQ][DD + 1];
    __shared__ float Ks[AT_TS][DD + 1];
    __shared__ float Vs[AT_TS][DD + 1];
    __shared__ float Ps[AT_TQ][AT_TS + 1];
    __shared__ float m_s[AT_TQ], l_s[AT_TQ], alpha_s[AT_TQ];

    int tid = threadIdx.x;

    // load Q tile
    for (int i = tid; i < AT_TQ * DD; i += 256) {
        int r = i >> 6, d = i & 63;
        Qs[r][d] = q[(size_t)(b * TT + qt0 + r) * EE + h * DD + d];
    }
    if (tid < AT_TQ) { m_s[tid] = -1e30f; l_s[tid] = 0.0f; }
    __syncthreads();

    float o_acc[4] = {0.f, 0.f, 0.f, 0.f};
    int d_own = tid & 63;            // also the s column this thread scores
    int r_base = (tid >> 6) * 4;     // {0,4,8,12}

    int n_tiles = (qt0 + AT_TQ - 1) / AT_TS + 1;

    for (int kt = 0; kt < n_tiles; kt++) {
        int s0 = kt * AT_TS;
        // load K,V tiles
        for (int i = tid; i < AT_TS * DD; i += 256) {
            int r = i >> 6, d = i & 63;
            size_t gi = (size_t)(b * TT + s0 + r) * EE + h * DD + d;
            Ks[r][d] = k[gi];
            Vs[r][d] = v[gi];
        }
        __syncthreads();

        // scores S[r_base+j][s=d_own]
        float sacc[4] = {0.f, 0.f, 0.f, 0.f};
#pragma unroll
        for (int d = 0; d < DD; d++) {
            float kv = Ks[d_own][d];
#pragma unroll
            for (int j = 0; j < 4; j++) sacc[j] = fmaf(Qs[r_base + j][d], kv, sacc[j]);
        }
        int s_glob = s0 + d_own;
#pragma unroll
        for (int j = 0; j < 4; j++) {
            int t_glob = qt0 + r_base + j;
            Ps[r_base + j][d_own] = (s_glob <= t_glob) ? sacc[j] : -1e30f;
        }
        __syncthreads();

        // online softmax: 8 warps x 2 rows
        int warp = tid >> 5, lane = tid & 31;
#pragma unroll
        for (int rw = 0; rw < 2; rw++) {
            int rr = warp * 2 + rw;
            float x0 = Ps[rr][lane], x1 = Ps[rr][lane + 32];
            float mx = fmaxf(x0, x1);
#pragma unroll
            for (int off = 16; off; off >>= 1)
                mx = fmaxf(mx, __shfl_xor_sync(0xffffffffu, mx, off));
            float m_old = m_s[rr];
            float m_new = fmaxf(m_old, mx);
            float e0 = __expf(x0 - m_new);
            float e1 = __expf(x1 - m_new);
            float sum = e0 + e1;
#pragma unroll
            for (int off = 16; off; off >>= 1)
                sum += __shfl_xor_sync(0xffffffffu, sum, off);
            Ps[rr][lane] = e0;
            Ps[rr][lane + 32] = e1;
            if (lane == 0) {
                float alpha = __expf(m_old - m_new);
                alpha_s[rr] = alpha;
                l_s[rr] = l_s[rr] * alpha + sum;
                m_s[rr] = m_new;
            }
        }
        __syncthreads();

        // O update
#pragma unroll
        for (int j = 0; j < 4; j++) o_acc[j] *= alpha_s[r_base + j];
#pragma unroll
        for (int s = 0; s < AT_TS; s++) {
            float vv = Vs[s][d_own];
#pragma unroll
            for (int j = 0; j < 4; j++) o_acc[j] = fmaf(Ps[r_base + j][s], vv, o_acc[j]);
        }
        __syncthreads();
    }

#pragma unroll
    for (int j = 0; j < 4; j++) {
        int r = r_base + j;
        o[(size_t)(b * TT + qt0 + r) * EE + h * DD + d_own] =
            o_acc[j] / l_s[r] * 0.125f;  // scale-after-softmax quirk: /sqrt(64)
    }
}

// ---------------- per-row logsumexp + per-row loss term -----------------------
__global__ __launch_bounds__(256) void lse_loss_kernel(const float* __restrict__ logits,
                                                       const int* __restrict__ targets,
                                                       float* __restrict__ lterms) {
    int row = blockIdx.x;
    const float* p = logits + (size_t)row * VV;
    float m = -1e30f, l = 0.0f;
    for (int i = threadIdx.x; i < VV; i += 256) {
        float x = p[i];
        if (x > m) { l = l * __expf(m - x) + 1.0f; m = x; }
        else       { l += __expf(x - m); }
    }
    __shared__ float ms[256], ls[256];
    ms[threadIdx.x] = m;
    ls[threadIdx.x] = l;
    __syncthreads();
    for (int s = 128; s; s >>= 1) {
        if (threadIdx.x < (unsigned)s) {
            float m2 = ms[threadIdx.x + s], l2 = ls[threadIdx.x + s];
            float M = fmaxf(ms[threadIdx.x], m2);
            ls[threadIdx.x] = ls[threadIdx.x] * __expf(ms[threadIdx.x] - M) + l2 * __expf(m2 - M);
            ms[threadIdx.x] = M;
        }
        __syncthreads();
    }
    if (threadIdx.x == 0) {
        float lse = ms[0] + logf(ls[0]);
        lterms[row] = lse - p[targets[row]];
    }
}

// deterministic final reduction
__global__ __launch_bounds__(256) void loss_reduce(const float* __restrict__ lterms,
                                                   float* __restrict__ out, int do_write) {
    __shared__ float s[256];
    float acc = 0.0f;
    for (int i = threadIdx.x; i < BT; i += 256) acc += lterms[i];
    s[threadIdx.x] = acc;
    __syncthreads();
    for (int st = 128; st; st >>= 1) {
        if (threadIdx.x < (unsigned)st) s[threadIdx.x] += s[threadIdx.x + st];
        __syncthreads();
    }
    if (threadIdx.x == 0 && do_write) out[0] = s[0] / (float)BT;
}

// ------------------------------- launch ---------------------------------------
extern "C" void kernel_launch(void* const* d_in, const int* in_sizes, int n_in,
                              void* d_out, int out_size) {
    const int*   tokens    = (const int*)d_in[0];
    const int*   targets   = (const int*)d_in[1];
    const float* tok_table = (const float*)d_in[2];
    const float* pos_emb   = (const float*)d_in[3];
    const float* Wq        = (const float*)d_in[4];
    const float* bq        = (const float*)d_in[5];
    const float* Wk        = (const float*)d_in[6];
    const float* bk        = (const float*)d_in[7];
    const float* Wv        = (const float*)d_in[8];
    const float* bv        = (const float*)d_in[9];
    const float* Wo        = (const float*)d_in[10];
    const float* bo        = (const float*)d_in[11];
    float* out = (float*)d_out;

    float *x, *q, *k, *v, *o, *lt;
    cudaGetSymbolAddress((void**)&x,  g_x);
    cudaGetSymbolAddress((void**)&q,  g_q);
    cudaGetSymbolAddress((void**)&k,  g_k);
    cudaGetSymbolAddress((void**)&v,  g_v);
    cudaGetSymbolAddress((void**)&o,  g_o);
    cudaGetSymbolAddress((void**)&lt, g_lterms);

    // 1) embedding
    embed_kernel<<<(BT * EE) / 256, 256>>>(tokens, tok_table, pos_emb, x);

    // 2) QKV projections (NT gemms, N=E)
    dim3 gqkv(EE / 128, BT / 128);
    gemm_nt<<<gqkv, 256>>>(x, Wq, bq, q, BT, EE, EE);
    gemm_nt<<<gqkv, 256>>>(x, Wk, bk, k, BT, EE, EE);
    gemm_nt<<<gqkv, 256>>>(x, Wv, bv, v, BT, EE, EE);

    // 3) causal attention
    attn_kernel<<<dim3(TT / AT_TQ, HH, BB), 256>>>(q, k, v, o);

    // 4) output projection -> logits straight into d_out
    dim3 glog(VV / 128, BT / 128);
    gemm_nt<<<glog, 256>>>(o, Wo, bo, out, BT, VV, EE);

    // 5) loss
    lse_loss_kernel<<<BT, 256>>>(out, targets, lt);
    int write_loss = (out_size > BT * VV) ? 1 : 0;
    loss_reduce<<<1, 256>>>(lt, out + (size_t)BT * VV, write_loss);
}

// round 5
// speedup vs baseline: 1.8272x; 1.8272x over previous
#include <cuda_runtime.h>
#include <cuda_bf16.h>
#include <cstdint>
#include <math.h>

// Problem constants
#define BB 2
#define TT 2048
#define EE 1024
#define HH 16
#define DD 64
#define VV 32000
#define BT (BB * TT)   // 4096

// ---------------- scratch (device globals; no allocations allowed) ------------
__device__ float g_x[BT * EE];
__device__ float g_q[BT * EE];
__device__ float g_k[BT * EE];
__device__ float g_v[BT * EE];
__device__ float g_o[BT * EE];
__device__ float g_lterms[BT];

// ---------------- helpers -----------------------------------------------------
__device__ __forceinline__ uint32_t f2tf32(float f) {
    uint32_t u;
    asm("cvt.rna.tf32.f32 %0, %1;" : "=r"(u) : "f"(f));
    return u;
}

__device__ __forceinline__ void mma_tf32(float* d, const uint4& a, const uint2& b) {
    asm volatile(
        "mma.sync.aligned.m16n8k8.row.col.f32.tf32.tf32.f32 "
        "{%0,%1,%2,%3}, {%4,%5,%6,%7}, {%8,%9}, {%0,%1,%2,%3};"
        : "+f"(d[0]), "+f"(d[1]), "+f"(d[2]), "+f"(d[3])
        : "r"(a.x), "r"(a.y), "r"(a.z), "r"(a.w), "r"(b.x), "r"(b.y));
}

// ---------------- embedding: x = tok_table[tokens] + pos_emb ------------------
__global__ void embed_kernel(const int* __restrict__ tokens,
                             const float* __restrict__ tok_table,
                             const float* __restrict__ pos_emb,
                             float* __restrict__ x) {
    int idx = blockIdx.x * blockDim.x + threadIdx.x;  // over BT*EE
    int bt = idx >> 10;          // /EE
    int e  = idx & (EE - 1);
    int t  = bt & (TT - 1);      // bt % TT
    int tok = tokens[bt];
    x[idx] = tok_table[tok * EE + e] + pos_emb[t * EE + e];
}

// ============ mma.sync tf32 NT GEMM: C[m,n] = sum_k A[m,k]B[n,k] + bias[n] ====
// CTA tile 128x128, BK=32 (4 k-steps of 8). 256 threads, 8 warps (2x4),
// warp tile 64x32 = 4x4 m16n8k8 fragments. fp32 accumulate in registers.
//
// SMEM layouts (fragment-native, conflict-free):
//   As: [R=8 (16-row blk)][ks=4][lane=32][4 floats]  -> per-lane {a0,a1,a2,a3}
//       a0=(g, t+8ks) a1=(g+8, t+8ks) a2=(g, t+4+8ks) a3=(g+8, t+4+8ks)
//   Bs: [Nb=16 (8-col blk)][ks=4][lane=32][2 floats] -> per-lane {b0,b1}
//       b0=(k=t+8ks, n=g) b1=(k=t+4+8ks, n=g)
// Each buffer 4096 floats (16KB); double buffered => 64KB dynamic smem total.

#define GM_BM 128
#define GM_BN 128
#define GM_BK 32
#define GM_BUF 4096     // floats per As or Bs buffer

__device__ __forceinline__ void gm_load_regs(const float* __restrict__ Aptr,
                                             const float* __restrict__ Bptr,
                                             int K, int k0, int tid,
                                             float4* pa, float4* pb) {
#pragma unroll
    for (int it = 0; it < 4; it++) {
        int q = tid + it * 256;
        int row = q >> 3, c = q & 7;
        pa[it] = *(const float4*)(Aptr + (size_t)row * K + k0 + c * 4);
        pb[it] = *(const float4*)(Bptr + (size_t)row * K + k0 + c * 4);
    }
}

__device__ __forceinline__ void gm_store_smem(float* __restrict__ As,
                                              float* __restrict__ Bs,
                                              const float4* pa, const float4* pb,
                                              int tid) {
#pragma unroll
    for (int it = 0; it < 4; it++) {
        int q = tid + it * 256;
        int row = q >> 3, c = q & 7;
        int ks = c >> 1, half = c & 1;
        // A scatter
        {
            int R = row >> 4, r16 = row & 15;
            int gA = r16 & 7, hi = r16 >> 3;
            int base = ((R * 4 + ks) * 32 + gA * 4) * 4 + half * 2 + hi;
            float v0 = pa[it].x, v1 = pa[it].y, v2 = pa[it].z, v3 = pa[it].w;
            ((uint32_t*)As)[base + 0 * 4] = f2tf32(v0);
            ((uint32_t*)As)[base + 1 * 4] = f2tf32(v1);
            ((uint32_t*)As)[base + 2 * 4] = f2tf32(v2);
            ((uint32_t*)As)[base + 3 * 4] = f2tf32(v3);
        }
        // B scatter
        {
            int Nb = row >> 3, gn = row & 7;
            int base = ((Nb * 4 + ks) * 32 + gn * 4) * 2 + half;
            float v0 = pb[it].x, v1 = pb[it].y, v2 = pb[it].z, v3 = pb[it].w;
            ((uint32_t*)Bs)[base + 0 * 2] = f2tf32(v0);
            ((uint32_t*)Bs)[base + 1 * 2] = f2tf32(v1);
            ((uint32_t*)Bs)[base + 2 * 2] = f2tf32(v2);
            ((uint32_t*)Bs)[base + 3 * 2] = f2tf32(v3);
        }
    }
}

__global__ __launch_bounds__(256) void gemm_mma(const float* __restrict__ A,
                                                const float* __restrict__ B,
                                                const float* __restrict__ bias,
                                                float* __restrict__ C,
                                                int M, int N, int K) {
    extern __shared__ float sm[];
    float* As = sm;            // [2][GM_BUF]
    float* Bs = sm + 2 * GM_BUF;

    int tid = threadIdx.x;
    int lane = tid & 31, wid = tid >> 5;
    int warp_m = wid >> 2, warp_n = wid & 3;
    int g = lane >> 2, t = lane & 3;

    int bm = blockIdx.x * GM_BM;
    int bn = blockIdx.y * GM_BN;

    const float* Aptr = A + (size_t)bm * K;
    const float* Bptr = B + (size_t)bn * K;

    float acc[4][4][4];
#pragma unroll
    for (int mi = 0; mi < 4; mi++)
#pragma unroll
        for (int ni = 0; ni < 4; ni++)
#pragma unroll
            for (int e = 0; e < 4; e++) acc[mi][ni][e] = 0.0f;

    float4 pa[4], pb[4];
    gm_load_regs(Aptr, Bptr, K, 0, tid, pa, pb);
    gm_store_smem(As, Bs, pa, pb, tid);
    __syncthreads();

    const int NCH = K / GM_BK;
    int abase = warp_m * 4;    // R offset
    int bbase = warp_n * 4;    // Nb offset

    for (int i = 0; i < NCH; i++) {
        int buf = i & 1;
        if (i + 1 < NCH)
            gm_load_regs(Aptr, Bptr, K, (i + 1) * GM_BK, tid, pa, pb);

        const float* Ab = As + buf * GM_BUF;
        const float* Bb = Bs + buf * GM_BUF;
#pragma unroll
        for (int ks = 0; ks < 4; ks++) {
            uint4 af[4];
            uint2 bf[4];
#pragma unroll
            for (int mi = 0; mi < 4; mi++)
                af[mi] = *(const uint4*)&Ab[((abase + mi) * 4 + ks) * 128 + lane * 4];
#pragma unroll
            for (int ni = 0; ni < 4; ni++)
                bf[ni] = *(const uint2*)&Bb[((bbase + ni) * 4 + ks) * 64 + lane * 2];
#pragma unroll
            for (int mi = 0; mi < 4; mi++)
#pragma unroll
                for (int ni = 0; ni < 4; ni++)
                    mma_tf32(acc[mi][ni], af[mi], bf[ni]);
        }
        __syncthreads();
        if (i + 1 < NCH) {
            gm_store_smem(As + (buf ^ 1) * GM_BUF, Bs + (buf ^ 1) * GM_BUF, pa, pb, tid);
            __syncthreads();
        }
    }

    // epilogue: add bias, store (float2 per fragment row)
    int m_base = bm + warp_m * 64;
    int n_base = bn + warp_n * 32;
#pragma unroll
    for (int mi = 0; mi < 4; mi++) {
#pragma unroll
        for (int ni = 0; ni < 4; ni++) {
            int r0 = m_base + mi * 16 + g;
            int col = n_base + ni * 8 + t * 2;
            float b0 = __ldg(&bias[col]);
            float b1 = __ldg(&bias[col + 1]);
            float2 o0 = make_float2(acc[mi][ni][0] + b0, acc[mi][ni][1] + b1);
            float2 o1 = make_float2(acc[mi][ni][2] + b0, acc[mi][ni][3] + b1);
            *(float2*)&C[(size_t)r0 * N + col] = o0;
            *(float2*)&C[(size_t)(r0 + 8) * N + col] = o1;
        }
    }
}

// ---------------- causal attention (flash-style, online softmax) --------------
#define AT_TQ 16
#define AT_TS 64

__global__ __launch_bounds__(256) void attn_kernel(const float* __restrict__ q,
                                                   const float* __restrict__ k,
                                                   const float* __restrict__ v,
                                                   float* __restrict__ o) {
    int qt0 = blockIdx.x * AT_TQ;
    int h = blockIdx.y;
    int b = blockIdx.z;

    __shared__ float Qs[AT_TQ][DD + 1];
    __shared__ float Ks[AT_TS][DD + 1];
    __shared__ float Vs[AT_TS][DD + 1];
    __shared__ float Ps[AT_TQ][AT_TS + 1];
    __shared__ float m_s[AT_TQ], l_s[AT_TQ], alpha_s[AT_TQ];

    int tid = threadIdx.x;

    for (int i = tid; i < AT_TQ * DD; i += 256) {
        int r = i >> 6, d = i & 63;
        Qs[r][d] = q[(size_t)(b * TT + qt0 + r) * EE + h * DD + d];
    }
    if (tid < AT_TQ) { m_s[tid] = -1e30f; l_s[tid] = 0.0f; }
    __syncthreads();

    float o_acc[4] = {0.f, 0.f, 0.f, 0.f};
    int d_own = tid & 63;
    int r_base = (tid >> 6) * 4;

    int n_tiles = (qt0 + AT_TQ - 1) / AT_TS + 1;

    for (int kt = 0; kt < n_tiles; kt++) {
        int s0 = kt * AT_TS;
        for (int i = tid; i < AT_TS * DD; i += 256) {
            int r = i >> 6, d = i & 63;
            size_t gi = (size_t)(b * TT + s0 + r) * EE + h * DD + d;
            Ks[r][d] = k[gi];
            Vs[r][d] = v[gi];
        }
        __syncthreads();

        float sacc[4] = {0.f, 0.f, 0.f, 0.f};
#pragma unroll
        for (int d = 0; d < DD; d++) {
            float kv = Ks[d_own][d];
#pragma unroll
            for (int j = 0; j < 4; j++) sacc[j] = fmaf(Qs[r_base + j][d], kv, sacc[j]);
        }
        int s_glob = s0 + d_own;
#pragma unroll
        for (int j = 0; j < 4; j++) {
            int t_glob = qt0 + r_base + j;
            Ps[r_base + j][d_own] = (s_glob <= t_glob) ? sacc[j] : -1e30f;
        }
        __syncthreads();

        int warp = tid >> 5, lane = tid & 31;
#pragma unroll
        for (int rw = 0; rw < 2; rw++) {
            int rr = warp * 2 + rw;
            float x0 = Ps[rr][lane], x1 = Ps[rr][lane + 32];
            float mx = fmaxf(x0, x1);
#pragma unroll
            for (int off = 16; off; off >>= 1)
                mx = fmaxf(mx, __shfl_xor_sync(0xffffffffu, mx, off));
            float m_old = m_s[rr];
            float m_new = fmaxf(m_old, mx);
            float e0 = __expf(x0 - m_new);
            float e1 = __expf(x1 - m_new);
            float sum = e0 + e1;
#pragma unroll
            for (int off = 16; off; off >>= 1)
                sum += __shfl_xor_sync(0xffffffffu, sum, off);
            Ps[rr][lane] = e0;
            Ps[rr][lane + 32] = e1;
            if (lane == 0) {
                float alpha = __expf(m_old - m_new);
                alpha_s[rr] = alpha;
                l_s[rr] = l_s[rr] * alpha + sum;
                m_s[rr] = m_new;
            }
        }
        __syncthreads();

#pragma unroll
        for (int j = 0; j < 4; j++) o_acc[j] *= alpha_s[r_base + j];
#pragma unroll
        for (int s = 0; s < AT_TS; s++) {
            float vv = Vs[s][d_own];
#pragma unroll
            for (int j = 0; j < 4; j++) o_acc[j] = fmaf(Ps[r_base + j][s], vv, o_acc[j]);
        }
        __syncthreads();
    }

#pragma unroll
    for (int j = 0; j < 4; j++) {
        int r = r_base + j;
        o[(size_t)(b * TT + qt0 + r) * EE + h * DD + d_own] =
            o_acc[j] / l_s[r] * 0.125f;
    }
}

// ---------------- per-row logsumexp + per-row loss term -----------------------
__global__ __launch_bounds__(256) void lse_loss_kernel(const float* __restrict__ logits,
                                                       const int* __restrict__ targets,
                                                       float* __restrict__ lterms) {
    int row = blockIdx.x;
    const float* p = logits + (size_t)row * VV;
    float m = -1e30f, l = 0.0f;
    for (int i = threadIdx.x; i < VV; i += 256) {
        float x = p[i];
        if (x > m) { l = l * __expf(m - x) + 1.0f; m = x; }
        else       { l += __expf(x - m); }
    }
    __shared__ float ms[256], ls[256];
    ms[threadIdx.x] = m;
    ls[threadIdx.x] = l;
    __syncthreads();
    for (int s = 128; s; s >>= 1) {
        if (threadIdx.x < (unsigned)s) {
            float m2 = ms[threadIdx.x + s], l2 = ls[threadIdx.x + s];
            float M = fmaxf(ms[threadIdx.x], m2);
            ls[threadIdx.x] = ls[threadIdx.x] * __expf(ms[threadIdx.x] - M) + l2 * __expf(m2 - M);
            ms[threadIdx.x] = M;
        }
        __syncthreads();
    }
    if (threadIdx.x == 0) {
        float lse = ms[0] + logf(ls[0]);
        lterms[row] = lse - p[targets[row]];
    }
}

__global__ __launch_bounds__(256) void loss_reduce(const float* __restrict__ lterms,
                                                   float* __restrict__ out, int do_write) {
    __shared__ float s[256];
    float acc = 0.0f;
    for (int i = threadIdx.x; i < BT; i += 256) acc += lterms[i];
    s[threadIdx.x] = acc;
    __syncthreads();
    for (int st = 128; st; st >>= 1) {
        if (threadIdx.x < (unsigned)st) s[threadIdx.x] += s[threadIdx.x + st];
        __syncthreads();
    }
    if (threadIdx.x == 0 && do_write) out[0] = s[0] / (float)BT;
}

// ------------------------------- launch ---------------------------------------
#define GSM_BYTES (4 * GM_BUF * sizeof(float))   // 64KB dynamic smem

extern "C" void kernel_launch(void* const* d_in, const int* in_sizes, int n_in,
                              void* d_out, int out_size) {
    const int*   tokens    = (const int*)d_in[0];
    const int*   targets   = (const int*)d_in[1];
    const float* tok_table = (const float*)d_in[2];
    const float* pos_emb   = (const float*)d_in[3];
    const float* Wq        = (const float*)d_in[4];
    const float* bq        = (const float*)d_in[5];
    const float* Wk        = (const float*)d_in[6];
    const float* bk        = (const float*)d_in[7];
    const float* Wv        = (const float*)d_in[8];
    const float* bv        = (const float*)d_in[9];
    const float* Wo        = (const float*)d_in[10];
    const float* bo        = (const float*)d_in[11];
    float* out = (float*)d_out;

    float *x, *q, *k, *v, *o, *lt;
    cudaGetSymbolAddress((void**)&x,  g_x);
    cudaGetSymbolAddress((void**)&q,  g_q);
    cudaGetSymbolAddress((void**)&k,  g_k);
    cudaGetSymbolAddress((void**)&v,  g_v);
    cudaGetSymbolAddress((void**)&o,  g_o);
    cudaGetSymbolAddress((void**)&lt, g_lterms);

    static int smem_set = 0;
    if (!smem_set) {
        cudaFuncSetAttribute(gemm_mma, cudaFuncAttributeMaxDynamicSharedMemorySize,
                             (int)GSM_BYTES);
        smem_set = 1;
    }

    // 1) embedding
    embed_kernel<<<(BT * EE) / 256, 256>>>(tokens, tok_table, pos_emb, x);

    // 2) QKV projections (tf32 mma.sync NT gemms, N=E)
    dim3 gqkv(BT / GM_BM, EE / GM_BN);   // m fastest
    gemm_mma<<<gqkv, 256, GSM_BYTES>>>(x, Wq, bq, q, BT, EE, EE);
    gemm_mma<<<gqkv, 256, GSM_BYTES>>>(x, Wk, bk, k, BT, EE, EE);
    gemm_mma<<<gqkv, 256, GSM_BYTES>>>(x, Wv, bv, v, BT, EE, EE);

    // 3) causal attention
    attn_kernel<<<dim3(TT / AT_TQ, HH, BB), 256>>>(q, k, v, o);

    // 4) output projection -> logits straight into d_out
    dim3 glog(BT / GM_BM, VV / GM_BN);   // m fastest: Wo tile stays L2-resident
    gemm_mma<<<glog, 256, GSM_BYTES>>>(o, Wo, bo, out, BT, VV, EE);

    // 5) loss
    lse_loss_kernel<<<BT, 256>>>(out, targets, lt);
    int write_loss = (out_size > BT * VV) ? 1 : 0;
    loss_reduce<<<1, 256>>>(lt, out + (size_t)BT * VV, write_loss);
}